// round 2
// baseline (speedup 1.0000x reference)
#include <cuda_runtime.h>
#include <math.h>

#define NH   256     // B*H = 8*32 heads
#define SLEN 4096
#define DIM  128
#define RSEL 16
#define KSEL 256

// ---- device scratch (no allocations allowed) ----
__device__ float g_qmask[NH * DIM];   // Q with non-top-r dims zeroed
__device__ float g_rscale[NH];        // 1/scale
__device__ float g_scores[NH * SLEN]; // masked QK_hat / scale
__device__ float g_logits[NH * SLEN]; // full Q.K / sqrt(D)
__device__ float g_w[NH * SLEN];      // dense softmax weights (0 for unselected)
__device__ float g_vmean[NH * DIM];   // un-normalized V column sums
__device__ float g_y[NH * DIM];       // weighted V sums
__device__ float g_alpha[NH];

__device__ __forceinline__ unsigned fkey(float f) {
    unsigned u = __float_as_uint(f);
    return (u & 0x80000000u) ? ~u : (u | 0x80000000u);  // order-preserving float->uint
}

// ============================================================
// K1: per head — top-16 |Q| dims, scale, masked Q; zero accumulators
// grid NH, block 128
// ============================================================
__global__ void prep_kernel(const float* __restrict__ Q) {
    int h = blockIdx.x, t = threadIdx.x;
    __shared__ float aq[DIM];
    __shared__ float rv[DIM];
    __shared__ int   ri[DIM];
    __shared__ unsigned char sel[DIM];
    __shared__ float s_sumall, s_sumtop;

    float q = Q[h * DIM + t];
    float a = fabsf(q);
    aq[t] = a; sel[t] = 0;
    g_vmean[h * DIM + t] = 0.f;   // zeroed before vpass atomics (stream-ordered)
    g_y[h * DIM + t] = 0.f;
    rv[t] = a;
    __syncthreads();
    for (int s = 64; s > 0; s >>= 1) { if (t < s) rv[t] += rv[t + s]; __syncthreads(); }
    if (t == 0) s_sumall = rv[0];
    __syncthreads();

    float sumtop = 0.f;
    for (int it = 0; it < RSEL; it++) {
        rv[t] = aq[t]; ri[t] = t;
        __syncthreads();
        for (int s = 64; s > 0; s >>= 1) {
            if (t < s) {
                float v2 = rv[t + s]; int i2 = ri[t + s];
                if (v2 > rv[t] || (v2 == rv[t] && i2 < ri[t])) { rv[t] = v2; ri[t] = i2; }
            }
            __syncthreads();
        }
        if (t == 0) { sel[ri[0]] = 1; sumtop += rv[0]; aq[ri[0]] = -1.f; }
        __syncthreads();
    }
    if (t == 0) s_sumtop = sumtop;
    __syncthreads();

    g_qmask[h * DIM + t] = sel[t] ? q : 0.f;
    if (t == 0) g_rscale[h] = rsqrtf((float)DIM * s_sumtop / s_sumall);
}

// ============================================================
// K2: single pass over K. For every row s:
//   g_scores = dot(qmask, K_s) / scale   (approx logits for select)
//   g_logits = dot(Q, K_s) / sqrt(D)     (exact logits, reused later)
// grid NH*4, block 512 (16 warps, 64 contiguous rows each), MLP=8
// ============================================================
__global__ __launch_bounds__(512) void kpass_kernel(const float* __restrict__ Kg,
                                                    const float* __restrict__ Q) {
    int bid = blockIdx.x; int h = bid >> 2; int chunk = bid & 3;
    int t = threadIdx.x; int w = t >> 5; int lane = t & 31;
    __shared__ float4 qm4[32];
    __shared__ float4 qf4[32];
    __shared__ float s_rs;
    if (t < 32) {
        qm4[t] = ((const float4*)(g_qmask + h * DIM))[t];
        qf4[t] = ((const float4*)(Q + h * DIM))[t];
    }
    if (t == 0) s_rs = g_rscale[h];
    __syncthreads();
    float4 qm = qm4[lane];
    float4 qf = qf4[lane];
    float rs = s_rs;
    const float invsq = 0.08838834764831845f; // 1/sqrt(128)
    const float4* Kr = (const float4*)(Kg + (size_t)h * SLEN * DIM);
    int base = chunk * 1024 + w * 64;           // warp's contiguous 64-row block
    float* scp = g_scores + h * SLEN + base;
    float* lgp = g_logits + h * SLEN + base;

    for (int it = 0; it < 64; it += 8) {
        float4 kv[8];
#pragma unroll
        for (int j = 0; j < 8; j++)
            kv[j] = Kr[(size_t)(base + it + j) * 32 + lane];
        float dm[8], df[8];
#pragma unroll
        for (int j = 0; j < 8; j++) {
            dm[j] = qm.x * kv[j].x + qm.y * kv[j].y + qm.z * kv[j].z + qm.w * kv[j].w;
            df[j] = qf.x * kv[j].x + qf.y * kv[j].y + qf.z * kv[j].z + qf.w * kv[j].w;
        }
#pragma unroll
        for (int off = 16; off; off >>= 1) {
#pragma unroll
            for (int j = 0; j < 8; j++) {
                dm[j] += __shfl_xor_sync(0xffffffffu, dm[j], off);
                df[j] += __shfl_xor_sync(0xffffffffu, df[j], off);
            }
        }
        if (lane == 0) {
#pragma unroll
            for (int j = 0; j < 8; j++) {
                scp[it + j] = dm[j] * rs;
                lgp[it + j] = df[j] * invsq;
            }
        }
    }
}

// ============================================================
// K3: per head — softmax stats over 4096 approx scores, radix
// top-256, alpha, softmax of exact logits on selected rows,
// scatter dense weight array. Pure L2/SMEM. grid NH, block 512
// ============================================================
__global__ __launch_bounds__(512) void select_kernel() {
    __shared__ float sc[SLEN];      // 16KB
    __shared__ float red[512];
    __shared__ int   hist[256];
    __shared__ int   scn[256];
    __shared__ int   idxs[KSEL];
    __shared__ float wts[KSEL];
    __shared__ unsigned s_prefix;
    __shared__ int s_need, s_cntA, s_cntB;
    __shared__ float s_mx, s_Z, s_m2, s_Z2;

    int h = blockIdx.x, t = threadIdx.x;
    for (int i = t; i < SLEN; i += 512) sc[i] = g_scores[h * SLEN + i];
    __syncthreads();

    // ---- max over 4096 ----
    float mx = -3.4e38f;
    for (int i = t; i < SLEN; i += 512) mx = fmaxf(mx, sc[i]);
    red[t] = mx; __syncthreads();
    for (int s = 256; s > 0; s >>= 1) { if (t < s) red[t] = fmaxf(red[t], red[t + s]); __syncthreads(); }
    if (t == 0) s_mx = red[0];
    __syncthreads();
    mx = s_mx;

    // ---- Z = sum exp ----
    float z = 0.f;
    for (int i = t; i < SLEN; i += 512) z += __expf(sc[i] - mx);
    red[t] = z; __syncthreads();
    for (int s = 256; s > 0; s >>= 1) { if (t < s) red[t] += red[t + s]; __syncthreads(); }
    if (t == 0) s_Z = red[0];
    __syncthreads();

    // ---- exact radix top-KSEL threshold on fkey(score) ----
    unsigned prefix = 0; int need = KSEL;
    for (int pass = 0; pass < 4; pass++) {
        int shift = 24 - 8 * pass;
        if (t < 256) hist[t] = 0;
        __syncthreads();
        for (int i = t; i < SLEN; i += 512) {
            unsigned u = fkey(sc[i]);
            unsigned hb = (pass == 0) ? 0u : (u >> (shift + 8));
            unsigned pb = (pass == 0) ? 0u : (prefix >> (shift + 8));
            if (hb == pb) atomicAdd(&hist[(u >> shift) & 255], 1);
        }
        __syncthreads();
        if (t < 256) scn[t] = hist[t];
        __syncthreads();
        for (int off = 1; off < 256; off <<= 1) {     // inclusive suffix sum
            int v = 0;
            if (t < 256) v = scn[t] + ((t + off < 256) ? scn[t + off] : 0);
            __syncthreads();
            if (t < 256) scn[t] = v;
            __syncthreads();
        }
        if (t < 256) {
            int above = (t + 1 < 256) ? scn[t + 1] : 0;   // strictly higher buckets
            if (above < need && above + hist[t] >= need) {
                s_prefix = prefix | ((unsigned)t << shift);
                s_need = need - above;
            }
        }
        __syncthreads();
        prefix = s_prefix; need = s_need;
        __syncthreads();
    }
    unsigned T = prefix;

    // ---- compact indices: all > T, then fill with == T ----
    if (t == 0) s_cntA = 0;
    __syncthreads();
    for (int i = t; i < SLEN; i += 512)
        if (fkey(sc[i]) > T) { int p = atomicAdd(&s_cntA, 1); if (p < KSEL) idxs[p] = i; }
    __syncthreads();
    if (t == 0) s_cntB = s_cntA;
    __syncthreads();
    for (int i = t; i < SLEN; i += 512)
        if (fkey(sc[i]) == T) { int p = atomicAdd(&s_cntB, 1); if (p < KSEL) idxs[p] = i; }
    __syncthreads();

    // ---- alpha = sum of top-k approx softmax probs ----
    float an = (t < KSEL) ? __expf(sc[idxs[t]] - mx) : 0.f;
    red[t] = an; __syncthreads();
    for (int s = 256; s > 0; s >>= 1) { if (t < s) red[t] += red[t + s]; __syncthreads(); }
    if (t == 0) g_alpha[h] = red[0] / s_Z;
    __syncthreads();

    // ---- softmax of exact logits over the selected 256 rows ----
    float l = (t < KSEL) ? g_logits[h * SLEN + idxs[t]] : -3.4e38f;
    red[t] = l; __syncthreads();
    for (int s = 256; s > 0; s >>= 1) { if (t < s) red[t] = fmaxf(red[t], red[t + s]); __syncthreads(); }
    if (t == 0) s_m2 = red[0];
    __syncthreads();
    float e = (t < KSEL) ? __expf(l - s_m2) : 0.f;
    red[t] = e; __syncthreads();
    for (int s = 256; s > 0; s >>= 1) { if (t < s) red[t] += red[t + s]; __syncthreads(); }
    if (t == 0) s_Z2 = red[0];
    __syncthreads();
    if (t < KSEL) wts[t] = e / s_Z2;
    __syncthreads();

    // ---- zero dense weight row, then scatter selected weights ----
    for (int i = t; i < SLEN; i += 512) g_w[h * SLEN + i] = 0.f;
    __syncthreads();
    if (t < KSEL) g_w[h * SLEN + idxs[t]] = wts[t];
}

// ============================================================
// K4: single pass over V. Accumulates plain column sums (V_mean)
// and weighted sums (y) simultaneously — weights are dense in L2.
// grid NH*8, block 256, MLP=8
// ============================================================
__global__ __launch_bounds__(256) void vpass_kernel(const float* __restrict__ Vg) {
    int bid = blockIdx.x; int h = bid >> 3; int chunk = bid & 7;
    int t = threadIdx.x; int g = t >> 5; int lane = t & 31;
    const float4* Vr = (const float4*)(Vg + (size_t)h * SLEN * DIM);
    const float* wrow = g_w + h * SLEN + chunk * 512;
    int base = chunk * 512;
    float4 am = make_float4(0.f, 0.f, 0.f, 0.f);
    float4 ay = make_float4(0.f, 0.f, 0.f, 0.f);

    for (int it = 0; it < 64; it += 8) {   // warp g owns rows g + 8*m; 8 rows in flight
        float4 v[8]; float wv[8];
#pragma unroll
        for (int j = 0; j < 8; j++) {
            int r = g + 8 * (it + j);
            v[j] = Vr[(size_t)(base + r) * 32 + lane];
            wv[j] = wrow[r];                 // uniform broadcast load
        }
#pragma unroll
        for (int j = 0; j < 8; j++) {
            am.x += v[j].x; am.y += v[j].y; am.z += v[j].z; am.w += v[j].w;
            ay.x += wv[j] * v[j].x; ay.y += wv[j] * v[j].y;
            ay.z += wv[j] * v[j].z; ay.w += wv[j] * v[j].w;
        }
    }
    __shared__ float4 bm[8][32];
    __shared__ float4 by[8][32];
    bm[g][lane] = am; by[g][lane] = ay;
    __syncthreads();
    if (t < 32) {
        float4 sm = bm[0][t], sy = by[0][t];
#pragma unroll
        for (int i = 1; i < 8; i++) {
            float4 a = bm[i][t], b = by[i][t];
            sm.x += a.x; sm.y += a.y; sm.z += a.z; sm.w += a.w;
            sy.x += b.x; sy.y += b.y; sy.z += b.z; sy.w += b.w;
        }
        float* dm = g_vmean + h * DIM + t * 4;
        float* dy = g_y + h * DIM + t * 4;
        atomicAdd(dm + 0, sm.x); atomicAdd(dm + 1, sm.y);
        atomicAdd(dm + 2, sm.z); atomicAdd(dm + 3, sm.w);
        atomicAdd(dy + 0, sy.x); atomicAdd(dy + 1, sy.y);
        atomicAdd(dy + 2, sy.z); atomicAdd(dy + 3, sy.w);
    }
}

// ============================================================
// K5: out = V_mean + alpha * (y - V_mean). grid NH, block 32
// ============================================================
__global__ void combine_kernel(float* __restrict__ out) {
    int h = blockIdx.x, t = threadIdx.x;
    const float inv = 1.f / (float)SLEN;
    float alpha = g_alpha[h];
    float4 vm = ((const float4*)(g_vmean + h * DIM))[t];
    float4 y  = ((const float4*)(g_y + h * DIM))[t];
    vm.x *= inv; vm.y *= inv; vm.z *= inv; vm.w *= inv;
    float4 o;
    o.x = vm.x + alpha * (y.x - vm.x);
    o.y = vm.y + alpha * (y.y - vm.y);
    o.z = vm.z + alpha * (y.z - vm.z);
    o.w = vm.w + alpha * (y.w - vm.w);
    ((float4*)out)[h * 32 + t] = o;
}

extern "C" void kernel_launch(void* const* d_in, const int* in_sizes, int n_in,
                              void* d_out, int out_size) {
    const float* Q = (const float*)d_in[0];
    const float* K = (const float*)d_in[1];
    const float* V = (const float*)d_in[2];
    // d_in[3] = mask (all true for this problem), d_in[4]=r, d_in[5]=k (constants)
    float* out = (float*)d_out;

    prep_kernel<<<NH, DIM>>>(Q);
    kpass_kernel<<<NH * 4, 512>>>(K, Q);
    select_kernel<<<NH, 512>>>();
    vpass_kernel<<<NH * 8, 256>>>(V);
    combine_kernel<<<NH, 32>>>(out);
}